// round 11
// baseline (speedup 1.0000x reference)
#include <cuda_runtime.h>
#include <cuda_fp16.h>
#include <cstdint>

#define S_LEN 2048
#define EMB   1024
#define NH    16
#define HD    64
#define BATCH 2
#define MTOT  (BATCH * S_LEN)   // 4096
#define NEG   (-10000.0f)

// Scratch (allocation-free: __device__ globals)
__device__ __align__(128) __half g_qkv16[(size_t)MTOT * 3 * EMB]; // q|k|v fp16
__device__ __align__(128) __half g_x16 [(size_t)MTOT * EMB];      // X fp16
__device__ __align__(128) __half g_wa16[(size_t)3 * EMB * EMB];   // W_attn fp16
__device__ __align__(128) __half g_wp16[(size_t)EMB * EMB];       // W_proj fp16
__device__ __align__(128) __half g_ctx16[(size_t)MTOT * EMB];     // ctx fp16

// ============================ helpers ======================================
__device__ __forceinline__ uint32_t smem_u32(const void* p) {
    uint32_t a;
    asm("{ .reg .u64 t; cvta.to.shared.u64 t, %1; cvt.u32.u64 %0, t; }"
        : "=r"(a) : "l"(p));
    return a;
}
__device__ __forceinline__ uint32_t packh2(float lo, float hi) {
    uint32_t r;
    asm("cvt.rn.f16x2.f32 %0, %1, %2;" : "=r"(r) : "f"(hi), "f"(lo));
    return r;
}
__device__ __forceinline__ void mma_f16(float& c0, float& c1, float& c2, float& c3,
                                        uint32_t a0, uint32_t a1, uint32_t a2, uint32_t a3,
                                        uint32_t b0, uint32_t b1) {
    asm volatile(
        "mma.sync.aligned.m16n8k16.row.col.f32.f16.f16.f32 "
        "{%0,%1,%2,%3}, {%4,%5,%6,%7}, {%8,%9}, {%0,%1,%2,%3};"
        : "+f"(c0), "+f"(c1), "+f"(c2), "+f"(c3)
        : "r"(a0), "r"(a1), "r"(a2), "r"(a3), "r"(b0), "r"(b1));
}
__device__ __forceinline__ void ldsm_x4(uint32_t& r0, uint32_t& r1,
                                        uint32_t& r2, uint32_t& r3, uint32_t addr) {
    asm volatile("ldmatrix.sync.aligned.m8n8.x4.shared.b16 {%0,%1,%2,%3}, [%4];"
                 : "=r"(r0), "=r"(r1), "=r"(r2), "=r"(r3) : "r"(addr));
}
__device__ __forceinline__ void ldsm_x4_t(uint32_t& r0, uint32_t& r1,
                                          uint32_t& r2, uint32_t& r3, uint32_t addr) {
    asm volatile("ldmatrix.sync.aligned.m8n8.x4.trans.shared.b16 {%0,%1,%2,%3}, [%4];"
                 : "=r"(r0), "=r"(r1), "=r"(r2), "=r"(r3) : "r"(addr));
}
__device__ __forceinline__ void cp_async16(uint32_t dst, const void* src) {
    asm volatile("cp.async.cg.shared.global [%0], [%1], 16;" :: "r"(dst), "l"(src));
}
__device__ __forceinline__ void cp_commit() {
    asm volatile("cp.async.commit_group;" ::: "memory");
}
__device__ __forceinline__ void cp_wait1() {
    asm volatile("cp.async.wait_group 1;" ::: "memory");
}
__device__ __forceinline__ void cp_wait0() {
    asm volatile("cp.async.wait_group 0;" ::: "memory");
}

// ====================== fp32 -> fp16 convert ===============================
__global__ void __launch_bounds__(256)
cvt_f2h(const float4* __restrict__ src, int n4, int which)
{
    __half2* dst = which == 0 ? (__half2*)g_x16
                 : which == 1 ? (__half2*)g_wa16 : (__half2*)g_wp16;
    const int i = blockIdx.x * blockDim.x + threadIdx.x;
    if (i < n4) {
        const float4 v = src[i];
        dst[2 * i]     = __floats2half2_rn(v.x, v.y);
        dst[2 * i + 1] = __floats2half2_rn(v.z, v.w);
    }
}

// ============ fp16 mma.sync GEMM (NT), GBK=64, 3-stage, ldmatrix ===========
// mode 0: A=g_x16, B=g_wa16, C=g_qkv16 (fp16) | mode 1: A=g_ctx16, B=g_wp16,
// C=C_ (fp32). CTA 128x128, BK=64, 256 threads, warp tile 64x32, m16n8k16.
// One barrier per 64-k chunk: 64 mma / 24 ldsm per warp per sync window.
#define GBM 128
#define GBN 128
#define GBK 64
#define SH  72                        // halves per smem row (144 B)
#define HTSZ (GBM * SH)               // 9216 halves per operand tile stage
#define NSTG 3
#define GEMM_SMEM (NSTG * 2 * HTSZ * 2)   // 110592 B

__global__ void __launch_bounds__(256, 2)
gemm_h(int mode, const float* __restrict__ bias, float* __restrict__ C_,
       int M, int N, int K)
{
    const __half* A  = mode == 0 ? g_x16  : g_ctx16;
    const __half* Bw = mode == 0 ? g_wa16 : g_wp16;

    extern __shared__ __half hsm[];
    __half* const As = hsm;
    __half* const Bs = hsm + NSTG * HTSZ;

    const int t = threadIdx.x;
    const int warp = t >> 5, lane = t & 31;
    const int wr = warp >> 2, wc = warp & 3;
    const int gid = lane >> 2, tig = lane & 3;
    const int bm = blockIdx.y * GBM, bn = blockIdx.x * GBN;
    const int lr = t >> 1, lc = (t & 1) * 32;   // 32 halves (64 B) per thread

    const int a_loff = ((lane & 7) + ((lane >> 3) & 1) * 8) * SH + ((lane >> 4) & 1) * 8;
    const int b_loff = ((lane & 7) + ((lane >> 4) & 1) * 8) * SH + ((lane >> 3) & 1) * 8;

    float acc[4][4][4];
#pragma unroll
    for (int mt = 0; mt < 4; mt++)
#pragma unroll
        for (int nt = 0; nt < 4; nt++)
#pragma unroll
            for (int i = 0; i < 4; i++) acc[mt][nt][i] = 0.f;

    const int nCk = K / GBK;   // 16

    auto issue = [&](int ck) {
        const int s = ck % NSTG;
        const int koff = ck * GBK;
        const __half* ga = A  + (size_t)(bm + lr) * K + koff + lc;
        const __half* gb = Bw + (size_t)(bn + lr) * K + koff + lc;
        const uint32_t sa = smem_u32(As + s * HTSZ + lr * SH + lc);
        const uint32_t sb = smem_u32(Bs + s * HTSZ + lr * SH + lc);
#pragma unroll
        for (int q = 0; q < 4; q++) {
            cp_async16(sa + 16 * q, ga + 8 * q);
            cp_async16(sb + 16 * q, gb + 8 * q);
        }
        cp_commit();
    };

    issue(0);
    issue(1);

    for (int ck = 0; ck < nCk; ++ck) {
        const int rem = nCk - 1 - ck;
        if (rem >= 1) cp_wait1();
        else          cp_wait0();
        __syncthreads();
        if (rem >= 2) issue(ck + 2);

        const uint32_t as0 = smem_u32(As + (ck % NSTG) * HTSZ);
        const uint32_t bs0 = smem_u32(Bs + (ck % NSTG) * HTSZ);
#pragma unroll
        for (int k0 = 0; k0 < GBK; k0 += 16) {
            uint32_t bf[4][2];
#pragma unroll
            for (int np = 0; np < 2; np++) {
                const uint32_t addr =
                    bs0 + 2 * (b_loff + (wc * 32 + np * 16) * SH + k0);
                ldsm_x4(bf[2 * np][0], bf[2 * np][1],
                        bf[2 * np + 1][0], bf[2 * np + 1][1], addr);
            }
#pragma unroll
            for (int mt = 0; mt < 4; mt++) {
                uint32_t a0, a1, a2, a3;
                const uint32_t addr =
                    as0 + 2 * (a_loff + (wr * 64 + mt * 16) * SH + k0);
                ldsm_x4(a0, a1, a2, a3, addr);
#pragma unroll
                for (int nt = 0; nt < 4; nt++)
                    mma_f16(acc[mt][nt][0], acc[mt][nt][1],
                            acc[mt][nt][2], acc[mt][nt][3],
                            a0, a1, a2, a3, bf[nt][0], bf[nt][1]);
            }
        }
    }

    // epilogue
#pragma unroll
    for (int mt = 0; mt < 4; mt++) {
        const int row0 = bm + wr * 64 + mt * 16 + gid;
#pragma unroll
        for (int nt = 0; nt < 4; nt++) {
            const int col = bn + wc * 32 + nt * 8 + tig * 2;
            const float b0 = bias[col], b1 = bias[col + 1];
            if (mode == 0) {
                __half2 v0 = __floats2half2_rn(acc[mt][nt][0] + b0, acc[mt][nt][1] + b1);
                __half2 v1 = __floats2half2_rn(acc[mt][nt][2] + b0, acc[mt][nt][3] + b1);
                *(__half2*)&g_qkv16[(size_t)row0 * N + col] = v0;
                *(__half2*)&g_qkv16[(size_t)(row0 + 8) * N + col] = v1;
            } else {
                float2 v0 = make_float2(acc[mt][nt][0] + b0, acc[mt][nt][1] + b1);
                float2 v1 = make_float2(acc[mt][nt][2] + b0, acc[mt][nt][3] + b1);
                *(float2*)&C_[(size_t)row0 * N + col] = v0;
                *(float2*)&C_[(size_t)(row0 + 8) * N + col] = v1;
            }
        }
    }
}

// ================= fp16 tensor-core flash attention (R10, unchanged) =======
#define KSTR 72
#define KTILE (64 * KSTR)
#define FLASH_SMEM (4 * KTILE * 2 + 512)   // 37376 B

__global__ void __launch_bounds__(128)
flash_h(const int* __restrict__ amask)
{
    extern __shared__ __half hsm[];
    const int qb = 31 - (int)blockIdx.x;
    const int h  = blockIdx.y;
    const int b  = blockIdx.z;
    const int t  = threadIdx.x;
    const int wid = t >> 5, lane = t & 31;
    const int g = lane >> 2, tg = lane & 3;

    __half* const kbuf[2] = { hsm,             hsm + 2 * KTILE };
    __half* const vbuf[2] = { hsm + KTILE,     hsm + 3 * KTILE };
    float*  const msb     = (float*)(hsm + 4 * KTILE);

    const int qrlo = qb * 64 + wid * 16 + g;
    const __half* qlo = g_qkv16 + ((size_t)(b * S_LEN) + qrlo) * 3072 + h * 64;
    const __half* qhi = qlo + (size_t)8 * 3072;
    const __half2 sc2 = __floats2half2_rn(0.125f, 0.125f);
    uint32_t qf[4][4];
#pragma unroll
    for (int kk = 0; kk < 4; kk++) {
        __half2 v0 = __hmul2(*(const __half2*)&qlo[16 * kk + 2 * tg], sc2);
        __half2 v1 = __hmul2(*(const __half2*)&qhi[16 * kk + 2 * tg], sc2);
        __half2 v2 = __hmul2(*(const __half2*)&qlo[16 * kk + 2 * tg + 8], sc2);
        __half2 v3 = __hmul2(*(const __half2*)&qhi[16 * kk + 2 * tg + 8], sc2);
        qf[kk][0] = *(uint32_t*)&v0; qf[kk][1] = *(uint32_t*)&v1;
        qf[kk][2] = *(uint32_t*)&v2; qf[kk][3] = *(uint32_t*)&v3;
    }

    const int kf_loff = ((lane & 7) + ((lane >> 4) & 1) * 8) * KSTR
                        + ((lane >> 3) & 1) * 8;
    const int vf_loff = (lane & 15) * KSTR + ((lane >> 4) & 1) * 8;

    float oa[8][4];
#pragma unroll
    for (int j = 0; j < 8; j++)
#pragma unroll
        for (int i = 0; i < 4; i++) oa[j][i] = 0.f;
    float m0 = -1e30f, m1 = -1e30f, l0 = 0.f, l1 = 0.f;

    auto issue = [&](int jt) {
        const int buf = jt & 1;
        __half* ks = kbuf[buf];
        __half* vs = vbuf[buf];
        const int j0 = jt * 64;
#pragma unroll
        for (int u = 0; u < 4; u++) {
            const int idx = t + 128 * u;
            const int r = idx >> 3, c8 = (idx & 7) * 8;
            const __half* src = g_qkv16 + ((size_t)(b * S_LEN) + j0 + r) * 3072
                                + 1024 + h * 64 + c8;
            cp_async16(smem_u32(ks + r * KSTR + c8), src);
            cp_async16(smem_u32(vs + r * KSTR + c8), src + 1024);
        }
        if (t < 64)
            msb[buf * 64 + t] = amask[b * S_LEN + j0 + t] ? 0.f : NEG;
        cp_commit();
    };

    issue(0);

    for (int jt = 0; jt <= qb; jt++) {
        if (jt < qb) { issue(jt + 1); cp_wait1(); }
        else         { cp_wait0(); }
        __syncthreads();

        const int buf = jt & 1;
        const uint32_t ks0 = smem_u32(kbuf[buf]);
        const uint32_t vs0 = smem_u32(vbuf[buf]);
        const float*   mb  = msb + buf * 64;

        float sc[8][4];
#pragma unroll
        for (int j = 0; j < 8; j++)
#pragma unroll
            for (int i = 0; i < 4; i++) sc[j][i] = 0.f;
#pragma unroll
        for (int kk = 0; kk < 4; kk++) {
            uint32_t kf[8][2];
#pragma unroll
            for (int nb = 0; nb < 4; nb++) {
                const uint32_t addr =
                    ks0 + 2 * (kf_loff + nb * 16 * KSTR + kk * 16);
                ldsm_x4(kf[2 * nb][0], kf[2 * nb][1],
                        kf[2 * nb + 1][0], kf[2 * nb + 1][1], addr);
            }
#pragma unroll
            for (int j = 0; j < 8; j++)
                mma_f16(sc[j][0], sc[j][1], sc[j][2], sc[j][3],
                        qf[kk][0], qf[kk][1], qf[kk][2], qf[kk][3],
                        kf[j][0], kf[j][1]);
        }

        const bool diag = (jt == qb);
        const int rlo = wid * 16 + g, rhi = rlo + 8;
        float tm0 = -1e30f, tm1 = -1e30f;
#pragma unroll
        for (int j = 0; j < 8; j++) {
            const float2 mm = *(const float2*)&mb[8 * j + 2 * tg];
            float c0 = sc[j][0] + mm.x, c1 = sc[j][1] + mm.y;
            float c2 = sc[j][2] + mm.x, c3 = sc[j][3] + mm.y;
            if (diag) {
                const int kv = 8 * j + 2 * tg;
                c0 = (kv     > rlo) ? NEG : c0;
                c1 = (kv + 1 > rlo) ? NEG : c1;
                c2 = (kv     > rhi) ? NEG : c2;
                c3 = (kv + 1 > rhi) ? NEG : c3;
            }
            sc[j][0] = c0; sc[j][1] = c1; sc[j][2] = c2; sc[j][3] = c3;
            tm0 = fmaxf(tm0, fmaxf(c0, c1));
            tm1 = fmaxf(tm1, fmaxf(c2, c3));
        }
        tm0 = fmaxf(tm0, __shfl_xor_sync(0xffffffffu, tm0, 1));
        tm0 = fmaxf(tm0, __shfl_xor_sync(0xffffffffu, tm0, 2));
        tm1 = fmaxf(tm1, __shfl_xor_sync(0xffffffffu, tm1, 1));
        tm1 = fmaxf(tm1, __shfl_xor_sync(0xffffffffu, tm1, 2));

        const float mn0 = fmaxf(m0, tm0), mn1 = fmaxf(m1, tm1);
        const float al0 = __expf(m0 - mn0), al1 = __expf(m1 - mn1);
        float s0 = 0.f, s1 = 0.f;
#pragma unroll
        for (int j = 0; j < 8; j++) {
            sc[j][0] = __expf(sc[j][0] - mn0);
            sc[j][1] = __expf(sc[j][1] - mn0);
            sc[j][2] = __expf(sc[j][2] - mn1);
            sc[j][3] = __expf(sc[j][3] - mn1);
            s0 += sc[j][0] + sc[j][1];
            s1 += sc[j][2] + sc[j][3];
        }
        s0 += __shfl_xor_sync(0xffffffffu, s0, 1);
        s0 += __shfl_xor_sync(0xffffffffu, s0, 2);
        s1 += __shfl_xor_sync(0xffffffffu, s1, 1);
        s1 += __shfl_xor_sync(0xffffffffu, s1, 2);
        l0 = l0 * al0 + s0; l1 = l1 * al1 + s1;
        m0 = mn0; m1 = mn1;
#pragma unroll
        for (int j = 0; j < 8; j++) {
            oa[j][0] *= al0; oa[j][1] *= al0;
            oa[j][2] *= al1; oa[j][3] *= al1;
        }

#pragma unroll
        for (int kk = 0; kk < 4; kk++) {
            const uint32_t a0 = packh2(sc[2 * kk][0],     sc[2 * kk][1]);
            const uint32_t a1 = packh2(sc[2 * kk][2],     sc[2 * kk][3]);
            const uint32_t a2 = packh2(sc[2 * kk + 1][0], sc[2 * kk + 1][1]);
            const uint32_t a3 = packh2(sc[2 * kk + 1][2], sc[2 * kk + 1][3]);
#pragma unroll
            for (int db = 0; db < 4; db++) {
                uint32_t b00, b01, b10, b11;
                const uint32_t addr =
                    vs0 + 2 * (vf_loff + kk * 16 * KSTR + db * 16);
                ldsm_x4_t(b00, b01, b10, b11, addr);
                mma_f16(oa[2 * db][0], oa[2 * db][1], oa[2 * db][2], oa[2 * db][3],
                        a0, a1, a2, a3, b00, b01);
                mma_f16(oa[2 * db + 1][0], oa[2 * db + 1][1],
                        oa[2 * db + 1][2], oa[2 * db + 1][3],
                        a0, a1, a2, a3, b10, b11);
            }
        }
        __syncthreads();
    }

    const float i0 = 1.f / l0, i1 = 1.f / l1;
    __half2* olo = (__half2*)(g_ctx16 + ((size_t)(b * S_LEN) + qrlo) * EMB + h * 64);
    __half2* ohi = (__half2*)((__half*)olo + (size_t)8 * EMB);
#pragma unroll
    for (int j2 = 0; j2 < 8; j2++) {
        const int d2 = 4 * j2 + tg;
        olo[d2] = __floats2half2_rn(oa[j2][0] * i0, oa[j2][1] * i0);
        ohi[d2] = __floats2half2_rn(oa[j2][2] * i1, oa[j2][3] * i1);
    }
}

// =============================== Launch ====================================
extern "C" void kernel_launch(void* const* d_in, const int* in_sizes, int n_in,
                              void* d_out, int out_size)
{
    const float* X     = (const float*)d_in[0];
    const int*   amask = (const int*)  d_in[1];
    const float* Wa    = (const float*)d_in[2];
    const float* ba    = (const float*)d_in[3];
    const float* Wp    = (const float*)d_in[4];
    const float* bp    = (const float*)d_in[5];
    float* out = (float*)d_out;

    cudaFuncSetAttribute(gemm_h, cudaFuncAttributeMaxDynamicSharedMemorySize,
                         GEMM_SMEM);
    cudaFuncSetAttribute(flash_h, cudaFuncAttributeMaxDynamicSharedMemorySize,
                         FLASH_SMEM);

    // 0) convert inputs to fp16
    {
        const int nx = MTOT * EMB / 4, na = 3 * EMB * EMB / 4, np = EMB * EMB / 4;
        cvt_f2h<<<(nx + 255) / 256, 256>>>((const float4*)X, nx, 0);
        cvt_f2h<<<(na + 255) / 256, 256>>>((const float4*)Wa, na, 1);
        cvt_f2h<<<(np + 255) / 256, 256>>>((const float4*)Wp, np, 2);
    }
    // 1) qkv = X @ Wa^T + ba -> g_qkv16 (fp16)
    {
        dim3 grid(3 * EMB / GBN, MTOT / GBM);
        gemm_h<<<grid, 256, GEMM_SMEM>>>(0, ba, nullptr, MTOT, 3 * EMB, EMB);
    }
    // 2) attention -> g_ctx16 (fp16)
    {
        dim3 grid(S_LEN / 64, NH, BATCH);
        flash_h<<<grid, 128, FLASH_SMEM>>>(amask);
    }
    // 3) out = ctx @ Wp^T + bp (fp32)
    {
        dim3 grid(EMB / GBN, MTOT / GBM);
        gemm_h<<<grid, 256, GEMM_SMEM>>>(1, bp, out, MTOT, EMB, EMB);
    }
}

// round 12
// speedup vs baseline: 1.0352x; 1.0352x over previous
#include <cuda_runtime.h>
#include <cuda_fp16.h>
#include <cstdint>

#define S_LEN 2048
#define EMB   1024
#define NH    16
#define HD    64
#define BATCH 2
#define MTOT  (BATCH * S_LEN)   // 4096
#define NEG   (-10000.0f)

// Scratch (allocation-free: __device__ globals)
__device__ __align__(128) __half g_qkv16[(size_t)MTOT * 3 * EMB]; // q|k|v fp16
__device__ __align__(128) __half g_x16 [(size_t)MTOT * EMB];      // X fp16
__device__ __align__(128) __half g_wa16[(size_t)3 * EMB * EMB];   // W_attn fp16
__device__ __align__(128) __half g_wp16[(size_t)EMB * EMB];       // W_proj fp16
__device__ __align__(128) __half g_ctx16[(size_t)MTOT * EMB];     // ctx fp16

// ============================ helpers ======================================
__device__ __forceinline__ uint32_t smem_u32(const void* p) {
    uint32_t a;
    asm("{ .reg .u64 t; cvta.to.shared.u64 t, %1; cvt.u32.u64 %0, t; }"
        : "=r"(a) : "l"(p));
    return a;
}
__device__ __forceinline__ uint32_t packh2(float lo, float hi) {
    uint32_t r;
    asm("cvt.rn.f16x2.f32 %0, %1, %2;" : "=r"(r) : "f"(hi), "f"(lo));
    return r;
}
__device__ __forceinline__ void mma_f16(float& c0, float& c1, float& c2, float& c3,
                                        uint32_t a0, uint32_t a1, uint32_t a2, uint32_t a3,
                                        uint32_t b0, uint32_t b1) {
    asm volatile(
        "mma.sync.aligned.m16n8k16.row.col.f32.f16.f16.f32 "
        "{%0,%1,%2,%3}, {%4,%5,%6,%7}, {%8,%9}, {%0,%1,%2,%3};"
        : "+f"(c0), "+f"(c1), "+f"(c2), "+f"(c3)
        : "r"(a0), "r"(a1), "r"(a2), "r"(a3), "r"(b0), "r"(b1));
}
__device__ __forceinline__ void ldsm_x4(uint32_t& r0, uint32_t& r1,
                                        uint32_t& r2, uint32_t& r3, uint32_t addr) {
    asm volatile("ldmatrix.sync.aligned.m8n8.x4.shared.b16 {%0,%1,%2,%3}, [%4];"
                 : "=r"(r0), "=r"(r1), "=r"(r2), "=r"(r3) : "r"(addr));
}
__device__ __forceinline__ void ldsm_x4_t(uint32_t& r0, uint32_t& r1,
                                          uint32_t& r2, uint32_t& r3, uint32_t addr) {
    asm volatile("ldmatrix.sync.aligned.m8n8.x4.trans.shared.b16 {%0,%1,%2,%3}, [%4];"
                 : "=r"(r0), "=r"(r1), "=r"(r2), "=r"(r3) : "r"(addr));
}
__device__ __forceinline__ void cp_async16(uint32_t dst, const void* src) {
    asm volatile("cp.async.cg.shared.global [%0], [%1], 16;" :: "r"(dst), "l"(src));
}
__device__ __forceinline__ void cp_commit() {
    asm volatile("cp.async.commit_group;" ::: "memory");
}
__device__ __forceinline__ void cp_wait1() {
    asm volatile("cp.async.wait_group 1;" ::: "memory");
}
__device__ __forceinline__ void cp_wait0() {
    asm volatile("cp.async.wait_group 0;" ::: "memory");
}

// ====================== fp32 -> fp16 convert ===============================
__global__ void __launch_bounds__(256)
cvt_f2h(const float4* __restrict__ src, int n4, int which)
{
    __half2* dst = which == 0 ? (__half2*)g_x16
                 : which == 1 ? (__half2*)g_wa16 : (__half2*)g_wp16;
    const int i = blockIdx.x * blockDim.x + threadIdx.x;
    if (i < n4) {
        const float4 v = src[i];
        dst[2 * i]     = __floats2half2_rn(v.x, v.y);
        dst[2 * i + 1] = __floats2half2_rn(v.z, v.w);
    }
}

// ====== fp16 mma.sync GEMM (NT), 128x64x32 tile, 3 CTAs/SM ================
// mode 0: A=g_x16, B=g_wa16, C=g_qkv16 (fp16) | mode 1: A=g_ctx16, B=g_wp16,
// C=C_ (fp32). 256 threads, warp grid 4x2, warp tile 32x32, m16n8k16.
#define GBM 128
#define GBN 64
#define GBK 32
#define SH  40                        // halves per smem row (80 B)
#define ATSZ (GBM * SH)               // 5120 halves per A stage
#define BTSZ (GBN * SH)               // 2560 halves per B stage
#define NSTG 3
#define GEMM_SMEM (NSTG * (ATSZ + BTSZ) * 2)   // 46080 B

__global__ void __launch_bounds__(256, 3)
gemm_h(int mode, const float* __restrict__ bias, float* __restrict__ C_,
       int M, int N, int K)
{
    const __half* A  = mode == 0 ? g_x16  : g_ctx16;
    const __half* Bw = mode == 0 ? g_wa16 : g_wp16;

    extern __shared__ __half hsm[];
    __half* const As = hsm;                   // [NSTG][ATSZ]
    __half* const Bs = hsm + NSTG * ATSZ;     // [NSTG][BTSZ]

    const int t = threadIdx.x;
    const int warp = t >> 5, lane = t & 31;
    const int wr = warp >> 1, wc = warp & 1;   // warp grid 4 x 2
    const int gid = lane >> 2, tig = lane & 3;
    const int bm = blockIdx.y * GBM, bn = blockIdx.x * GBN;

    // cp.async mappings: A 128 rows x 64B (2 seg), B 64 rows x 64B (4 seg)
    const int lrA = t >> 1, lcA = (t & 1) * 16;
    const int lrB = t >> 2, lcB = (t & 3) * 8;

    const int a_loff = ((lane & 7) + ((lane >> 3) & 1) * 8) * SH + ((lane >> 4) & 1) * 8;
    const int b_loff = ((lane & 7) + ((lane >> 4) & 1) * 8) * SH + ((lane >> 3) & 1) * 8;

    float acc[2][4][4];
#pragma unroll
    for (int mt = 0; mt < 2; mt++)
#pragma unroll
        for (int nt = 0; nt < 4; nt++)
#pragma unroll
            for (int i = 0; i < 4; i++) acc[mt][nt][i] = 0.f;

    const int nCk = K / GBK;   // 32

    auto issue = [&](int ck) {
        const int s = ck % NSTG;
        const int koff = ck * GBK;
        const uint32_t sa = smem_u32(As + s * ATSZ + lrA * SH + lcA);
        const uint32_t sb = smem_u32(Bs + s * BTSZ + lrB * SH + lcB);
        cp_async16(sa,      A  + (size_t)(bm + lrA) * K + koff + lcA);
        cp_async16(sa + 16, A  + (size_t)(bm + lrA) * K + koff + lcA + 8);
        cp_async16(sb,      Bw + (size_t)(bn + lrB) * K + koff + lcB);
        cp_commit();
    };

    issue(0);
    issue(1);

    for (int ck = 0; ck < nCk; ++ck) {
        const int rem = nCk - 1 - ck;
        if (rem >= 1) cp_wait1();
        else          cp_wait0();
        __syncthreads();
        if (rem >= 2) issue(ck + 2);

        const uint32_t as0 = smem_u32(As + (ck % NSTG) * ATSZ);
        const uint32_t bs0 = smem_u32(Bs + (ck % NSTG) * BTSZ);
#pragma unroll
        for (int k0 = 0; k0 < GBK; k0 += 16) {
            uint32_t bf[4][2];
#pragma unroll
            for (int np = 0; np < 2; np++) {
                const uint32_t addr =
                    bs0 + 2 * (b_loff + (wc * 32 + np * 16) * SH + k0);
                ldsm_x4(bf[2 * np][0], bf[2 * np][1],
                        bf[2 * np + 1][0], bf[2 * np + 1][1], addr);
            }
#pragma unroll
            for (int mt = 0; mt < 2; mt++) {
                uint32_t a0, a1, a2, a3;
                const uint32_t addr =
                    as0 + 2 * (a_loff + (wr * 32 + mt * 16) * SH + k0);
                ldsm_x4(a0, a1, a2, a3, addr);
#pragma unroll
                for (int nt = 0; nt < 4; nt++)
                    mma_f16(acc[mt][nt][0], acc[mt][nt][1],
                            acc[mt][nt][2], acc[mt][nt][3],
                            a0, a1, a2, a3, bf[nt][0], bf[nt][1]);
            }
        }
    }

    // epilogue
#pragma unroll
    for (int mt = 0; mt < 2; mt++) {
        const int row0 = bm + wr * 32 + mt * 16 + gid;
#pragma unroll
        for (int nt = 0; nt < 4; nt++) {
            const int col = bn + wc * 32 + nt * 8 + tig * 2;
            const float b0 = bias[col], b1 = bias[col + 1];
            if (mode == 0) {
                __half2 v0 = __floats2half2_rn(acc[mt][nt][0] + b0, acc[mt][nt][1] + b1);
                __half2 v1 = __floats2half2_rn(acc[mt][nt][2] + b0, acc[mt][nt][3] + b1);
                *(__half2*)&g_qkv16[(size_t)row0 * N + col] = v0;
                *(__half2*)&g_qkv16[(size_t)(row0 + 8) * N + col] = v1;
            } else {
                float2 v0 = make_float2(acc[mt][nt][0] + b0, acc[mt][nt][1] + b1);
                float2 v1 = make_float2(acc[mt][nt][2] + b0, acc[mt][nt][3] + b1);
                *(float2*)&C_[(size_t)row0 * N + col] = v0;
                *(float2*)&C_[(size_t)(row0 + 8) * N + col] = v1;
            }
        }
    }
}

// ================= fp16 tensor-core flash attention (R10, unchanged) =======
#define KSTR 72
#define KTILE (64 * KSTR)
#define FLASH_SMEM (4 * KTILE * 2 + 512)   // 37376 B

__global__ void __launch_bounds__(128)
flash_h(const int* __restrict__ amask)
{
    extern __shared__ __half hsm[];
    const int qb = 31 - (int)blockIdx.x;
    const int h  = blockIdx.y;
    const int b  = blockIdx.z;
    const int t  = threadIdx.x;
    const int wid = t >> 5, lane = t & 31;
    const int g = lane >> 2, tg = lane & 3;

    __half* const kbuf[2] = { hsm,             hsm + 2 * KTILE };
    __half* const vbuf[2] = { hsm + KTILE,     hsm + 3 * KTILE };
    float*  const msb     = (float*)(hsm + 4 * KTILE);

    const int qrlo = qb * 64 + wid * 16 + g;
    const __half* qlo = g_qkv16 + ((size_t)(b * S_LEN) + qrlo) * 3072 + h * 64;
    const __half* qhi = qlo + (size_t)8 * 3072;
    const __half2 sc2 = __floats2half2_rn(0.125f, 0.125f);
    uint32_t qf[4][4];
#pragma unroll
    for (int kk = 0; kk < 4; kk++) {
        __half2 v0 = __hmul2(*(const __half2*)&qlo[16 * kk + 2 * tg], sc2);
        __half2 v1 = __hmul2(*(const __half2*)&qhi[16 * kk + 2 * tg], sc2);
        __half2 v2 = __hmul2(*(const __half2*)&qlo[16 * kk + 2 * tg + 8], sc2);
        __half2 v3 = __hmul2(*(const __half2*)&qhi[16 * kk + 2 * tg + 8], sc2);
        qf[kk][0] = *(uint32_t*)&v0; qf[kk][1] = *(uint32_t*)&v1;
        qf[kk][2] = *(uint32_t*)&v2; qf[kk][3] = *(uint32_t*)&v3;
    }

    const int kf_loff = ((lane & 7) + ((lane >> 4) & 1) * 8) * KSTR
                        + ((lane >> 3) & 1) * 8;
    const int vf_loff = (lane & 15) * KSTR + ((lane >> 4) & 1) * 8;

    float oa[8][4];
#pragma unroll
    for (int j = 0; j < 8; j++)
#pragma unroll
        for (int i = 0; i < 4; i++) oa[j][i] = 0.f;
    float m0 = -1e30f, m1 = -1e30f, l0 = 0.f, l1 = 0.f;

    auto issue = [&](int jt) {
        const int buf = jt & 1;
        __half* ks = kbuf[buf];
        __half* vs = vbuf[buf];
        const int j0 = jt * 64;
#pragma unroll
        for (int u = 0; u < 4; u++) {
            const int idx = t + 128 * u;
            const int r = idx >> 3, c8 = (idx & 7) * 8;
            const __half* src = g_qkv16 + ((size_t)(b * S_LEN) + j0 + r) * 3072
                                + 1024 + h * 64 + c8;
            cp_async16(smem_u32(ks + r * KSTR + c8), src);
            cp_async16(smem_u32(vs + r * KSTR + c8), src + 1024);
        }
        if (t < 64)
            msb[buf * 64 + t] = amask[b * S_LEN + j0 + t] ? 0.f : NEG;
        cp_commit();
    };

    issue(0);

    for (int jt = 0; jt <= qb; jt++) {
        if (jt < qb) { issue(jt + 1); cp_wait1(); }
        else         { cp_wait0(); }
        __syncthreads();

        const int buf = jt & 1;
        const uint32_t ks0 = smem_u32(kbuf[buf]);
        const uint32_t vs0 = smem_u32(vbuf[buf]);
        const float*   mb  = msb + buf * 64;

        float sc[8][4];
#pragma unroll
        for (int j = 0; j < 8; j++)
#pragma unroll
            for (int i = 0; i < 4; i++) sc[j][i] = 0.f;
#pragma unroll
        for (int kk = 0; kk < 4; kk++) {
            uint32_t kf[8][2];
#pragma unroll
            for (int nb = 0; nb < 4; nb++) {
                const uint32_t addr =
                    ks0 + 2 * (kf_loff + nb * 16 * KSTR + kk * 16);
                ldsm_x4(kf[2 * nb][0], kf[2 * nb][1],
                        kf[2 * nb + 1][0], kf[2 * nb + 1][1], addr);
            }
#pragma unroll
            for (int j = 0; j < 8; j++)
                mma_f16(sc[j][0], sc[j][1], sc[j][2], sc[j][3],
                        qf[kk][0], qf[kk][1], qf[kk][2], qf[kk][3],
                        kf[j][0], kf[j][1]);
        }

        const bool diag = (jt == qb);
        const int rlo = wid * 16 + g, rhi = rlo + 8;
        float tm0 = -1e30f, tm1 = -1e30f;
#pragma unroll
        for (int j = 0; j < 8; j++) {
            const float2 mm = *(const float2*)&mb[8 * j + 2 * tg];
            float c0 = sc[j][0] + mm.x, c1 = sc[j][1] + mm.y;
            float c2 = sc[j][2] + mm.x, c3 = sc[j][3] + mm.y;
            if (diag) {
                const int kv = 8 * j + 2 * tg;
                c0 = (kv     > rlo) ? NEG : c0;
                c1 = (kv + 1 > rlo) ? NEG : c1;
                c2 = (kv     > rhi) ? NEG : c2;
                c3 = (kv + 1 > rhi) ? NEG : c3;
            }
            sc[j][0] = c0; sc[j][1] = c1; sc[j][2] = c2; sc[j][3] = c3;
            tm0 = fmaxf(tm0, fmaxf(c0, c1));
            tm1 = fmaxf(tm1, fmaxf(c2, c3));
        }
        tm0 = fmaxf(tm0, __shfl_xor_sync(0xffffffffu, tm0, 1));
        tm0 = fmaxf(tm0, __shfl_xor_sync(0xffffffffu, tm0, 2));
        tm1 = fmaxf(tm1, __shfl_xor_sync(0xffffffffu, tm1, 1));
        tm1 = fmaxf(tm1, __shfl_xor_sync(0xffffffffu, tm1, 2));

        const float mn0 = fmaxf(m0, tm0), mn1 = fmaxf(m1, tm1);
        const float al0 = __expf(m0 - mn0), al1 = __expf(m1 - mn1);
        float s0 = 0.f, s1 = 0.f;
#pragma unroll
        for (int j = 0; j < 8; j++) {
            sc[j][0] = __expf(sc[j][0] - mn0);
            sc[j][1] = __expf(sc[j][1] - mn0);
            sc[j][2] = __expf(sc[j][2] - mn1);
            sc[j][3] = __expf(sc[j][3] - mn1);
            s0 += sc[j][0] + sc[j][1];
            s1 += sc[j][2] + sc[j][3];
        }
        s0 += __shfl_xor_sync(0xffffffffu, s0, 1);
        s0 += __shfl_xor_sync(0xffffffffu, s0, 2);
        s1 += __shfl_xor_sync(0xffffffffu, s1, 1);
        s1 += __shfl_xor_sync(0xffffffffu, s1, 2);
        l0 = l0 * al0 + s0; l1 = l1 * al1 + s1;
        m0 = mn0; m1 = mn1;
#pragma unroll
        for (int j = 0; j < 8; j++) {
            oa[j][0] *= al0; oa[j][1] *= al0;
            oa[j][2] *= al1; oa[j][3] *= al1;
        }

#pragma unroll
        for (int kk = 0; kk < 4; kk++) {
            const uint32_t a0 = packh2(sc[2 * kk][0],     sc[2 * kk][1]);
            const uint32_t a1 = packh2(sc[2 * kk][2],     sc[2 * kk][3]);
            const uint32_t a2 = packh2(sc[2 * kk + 1][0], sc[2 * kk + 1][1]);
            const uint32_t a3 = packh2(sc[2 * kk + 1][2], sc[2 * kk + 1][3]);
#pragma unroll
            for (int db = 0; db < 4; db++) {
                uint32_t b00, b01, b10, b11;
                const uint32_t addr =
                    vs0 + 2 * (vf_loff + kk * 16 * KSTR + db * 16);
                ldsm_x4_t(b00, b01, b10, b11, addr);
                mma_f16(oa[2 * db][0], oa[2 * db][1], oa[2 * db][2], oa[2 * db][3],
                        a0, a1, a2, a3, b00, b01);
                mma_f16(oa[2 * db + 1][0], oa[2 * db + 1][1],
                        oa[2 * db + 1][2], oa[2 * db + 1][3],
                        a0, a1, a2, a3, b10, b11);
            }
        }
        __syncthreads();
    }

    const float i0 = 1.f / l0, i1 = 1.f / l1;
    __half2* olo = (__half2*)(g_ctx16 + ((size_t)(b * S_LEN) + qrlo) * EMB + h * 64);
    __half2* ohi = (__half2*)((__half*)olo + (size_t)8 * EMB);
#pragma unroll
    for (int j2 = 0; j2 < 8; j2++) {
        const int d2 = 4 * j2 + tg;
        olo[d2] = __floats2half2_rn(oa[j2][0] * i0, oa[j2][1] * i0);
        ohi[d2] = __floats2half2_rn(oa[j2][2] * i1, oa[j2][3] * i1);
    }
}

// =============================== Launch ====================================
extern "C" void kernel_launch(void* const* d_in, const int* in_sizes, int n_in,
                              void* d_out, int out_size)
{
    const float* X     = (const float*)d_in[0];
    const int*   amask = (const int*)  d_in[1];
    const float* Wa    = (const float*)d_in[2];
    const float* ba    = (const float*)d_in[3];
    const float* Wp    = (const float*)d_in[4];
    const float* bp    = (const float*)d_in[5];
    float* out = (float*)d_out;

    cudaFuncSetAttribute(gemm_h, cudaFuncAttributeMaxDynamicSharedMemorySize,
                         GEMM_SMEM);
    cudaFuncSetAttribute(flash_h, cudaFuncAttributeMaxDynamicSharedMemorySize,
                         FLASH_SMEM);

    // 0) convert inputs to fp16
    {
        const int nx = MTOT * EMB / 4, na = 3 * EMB * EMB / 4, np = EMB * EMB / 4;
        cvt_f2h<<<(nx + 255) / 256, 256>>>((const float4*)X, nx, 0);
        cvt_f2h<<<(na + 255) / 256, 256>>>((const float4*)Wa, na, 1);
        cvt_f2h<<<(np + 255) / 256, 256>>>((const float4*)Wp, np, 2);
    }
    // 1) qkv = X @ Wa^T + ba -> g_qkv16 (fp16)
    {
        dim3 grid(3 * EMB / GBN, MTOT / GBM);
        gemm_h<<<grid, 256, GEMM_SMEM>>>(0, ba, nullptr, MTOT, 3 * EMB, EMB);
    }
    // 2) attention -> g_ctx16 (fp16)
    {
        dim3 grid(S_LEN / 64, NH, BATCH);
        flash_h<<<grid, 128, FLASH_SMEM>>>(amask);
    }
    // 3) out = ctx @ Wp^T + bp (fp32)
    {
        dim3 grid(EMB / GBN, MTOT / GBM);
        gemm_h<<<grid, 256, GEMM_SMEM>>>(1, bp, out, MTOT, EMB, EMB);
    }
}

// round 13
// speedup vs baseline: 1.0679x; 1.0315x over previous
#include <cuda_runtime.h>
#include <cuda_fp16.h>
#include <cstdint>

#define S_LEN 2048
#define EMB   1024
#define NH    16
#define HD    64
#define BATCH 2
#define MTOT  (BATCH * S_LEN)   // 4096
#define NEG   (-10000.0f)

// Scratch (allocation-free: __device__ globals)
__device__ __align__(128) __half g_qkv16[(size_t)MTOT * 3 * EMB]; // q|k|v fp16
__device__ __align__(128) __half g_x16 [(size_t)MTOT * EMB];      // X fp16
__device__ __align__(128) __half g_wa16[(size_t)3 * EMB * EMB];   // W_attn fp16
__device__ __align__(128) __half g_wp16[(size_t)EMB * EMB];       // W_proj fp16
__device__ __align__(128) __half g_ctx16[(size_t)MTOT * EMB];     // ctx fp16

// ============================ helpers ======================================
__device__ __forceinline__ uint32_t smem_u32(const void* p) {
    uint32_t a;
    asm("{ .reg .u64 t; cvta.to.shared.u64 t, %1; cvt.u32.u64 %0, t; }"
        : "=r"(a) : "l"(p));
    return a;
}
__device__ __forceinline__ uint32_t packh2(float lo, float hi) {
    uint32_t r;
    asm("cvt.rn.f16x2.f32 %0, %1, %2;" : "=r"(r) : "f"(hi), "f"(lo));
    return r;
}
__device__ __forceinline__ void mma_f16(float& c0, float& c1, float& c2, float& c3,
                                        uint32_t a0, uint32_t a1, uint32_t a2, uint32_t a3,
                                        uint32_t b0, uint32_t b1) {
    asm volatile(
        "mma.sync.aligned.m16n8k16.row.col.f32.f16.f16.f32 "
        "{%0,%1,%2,%3}, {%4,%5,%6,%7}, {%8,%9}, {%0,%1,%2,%3};"
        : "+f"(c0), "+f"(c1), "+f"(c2), "+f"(c3)
        : "r"(a0), "r"(a1), "r"(a2), "r"(a3), "r"(b0), "r"(b1));
}
__device__ __forceinline__ void ldsm_x4(uint32_t& r0, uint32_t& r1,
                                        uint32_t& r2, uint32_t& r3, uint32_t addr) {
    asm volatile("ldmatrix.sync.aligned.m8n8.x4.shared.b16 {%0,%1,%2,%3}, [%4];"
                 : "=r"(r0), "=r"(r1), "=r"(r2), "=r"(r3) : "r"(addr));
}
__device__ __forceinline__ void ldsm_x4_t(uint32_t& r0, uint32_t& r1,
                                          uint32_t& r2, uint32_t& r3, uint32_t addr) {
    asm volatile("ldmatrix.sync.aligned.m8n8.x4.trans.shared.b16 {%0,%1,%2,%3}, [%4];"
                 : "=r"(r0), "=r"(r1), "=r"(r2), "=r"(r3) : "r"(addr));
}
__device__ __forceinline__ void cp_async16(uint32_t dst, const void* src) {
    asm volatile("cp.async.cg.shared.global [%0], [%1], 16;" :: "r"(dst), "l"(src));
}
__device__ __forceinline__ void cp_commit() {
    asm volatile("cp.async.commit_group;" ::: "memory");
}
__device__ __forceinline__ void cp_wait1() {
    asm volatile("cp.async.wait_group 1;" ::: "memory");
}
__device__ __forceinline__ void cp_wait0() {
    asm volatile("cp.async.wait_group 0;" ::: "memory");
}

// ============ fp32 -> fp16 convert (single merged launch) ==================
__global__ void __launch_bounds__(256)
cvt_all(const float4* __restrict__ X, const float4* __restrict__ Wa,
        const float4* __restrict__ Wp, int nx, int na, int np)
{
    const int i = blockIdx.x * blockDim.x + threadIdx.x;
    const float4* src;
    __half2* dst;
    int j = i;
    if (j < nx)                { src = X;  dst = (__half2*)g_x16; }
    else if ((j -= nx) < na)   { src = Wa; dst = (__half2*)g_wa16; }
    else if ((j -= na) < np)   { src = Wp; dst = (__half2*)g_wp16; }
    else return;
    const float4 v = src[j];
    dst[2 * j]     = __floats2half2_rn(v.x, v.y);
    dst[2 * j + 1] = __floats2half2_rn(v.z, v.w);
}

// ====== fp16 mma.sync GEMM (NT), 128x128x32, persistent tile loop ==========
// mode 0: A=g_x16, B=g_wa16, C=g_qkv16 (fp16) | mode 1: A=g_ctx16, B=g_wp16,
// C=C_ (fp32). 256 threads, warp grid 2x4, warp tile 64x32, m16n8k16.
// Grid = min(nTiles, 2*SMs); each CTA loops over tiles -> no wave tail.
#define GBM 128
#define GBN 128
#define GBK 32
#define SH  40
#define HTSZ (GBM * SH)
#define NSTG 3
#define GEMM_SMEM (NSTG * 2 * HTSZ * 2)   // 61440 B

__global__ void __launch_bounds__(256, 2)
gemm_h(int mode, const float* __restrict__ bias, float* __restrict__ C_,
       int M, int N, int K)
{
    const __half* A  = mode == 0 ? g_x16  : g_ctx16;
    const __half* Bw = mode == 0 ? g_wa16 : g_wp16;

    extern __shared__ __half hsm[];
    __half* const As = hsm;
    __half* const Bs = hsm + NSTG * HTSZ;

    const int t = threadIdx.x;
    const int warp = t >> 5, lane = t & 31;
    const int wr = warp >> 2, wc = warp & 3;
    const int gid = lane >> 2, tig = lane & 3;
    const int lr = t >> 1, lc = (t & 1) * 16;

    const int a_loff = ((lane & 7) + ((lane >> 3) & 1) * 8) * SH + ((lane >> 4) & 1) * 8;
    const int b_loff = ((lane & 7) + ((lane >> 4) & 1) * 8) * SH + ((lane >> 3) & 1) * 8;

    const int nCk = K / GBK;
    const int nTileN = N / GBN;
    const int nTiles = (M / GBM) * nTileN;

    for (int tile = blockIdx.x; tile < nTiles; tile += gridDim.x) {
        const int bm = (tile / nTileN) * GBM;
        const int bn = (tile % nTileN) * GBN;
        const __half* ga0 = A  + (size_t)(bm + lr) * K + lc;
        const __half* gb0 = Bw + (size_t)(bn + lr) * K + lc;

        float acc[4][4][4];
#pragma unroll
        for (int mt = 0; mt < 4; mt++)
#pragma unroll
            for (int nt = 0; nt < 4; nt++)
#pragma unroll
                for (int i = 0; i < 4; i++) acc[mt][nt][i] = 0.f;

        auto issue = [&](int ck) {
            const int s = ck % NSTG;
            const int koff = ck * GBK;
            const uint32_t sa = smem_u32(As + s * HTSZ + lr * SH + lc);
            const uint32_t sb = smem_u32(Bs + s * HTSZ + lr * SH + lc);
            cp_async16(sa,      ga0 + koff);
            cp_async16(sa + 16, ga0 + koff + 8);
            cp_async16(sb,      gb0 + koff);
            cp_async16(sb + 16, gb0 + koff + 8);
            cp_commit();
        };

        issue(0);
        issue(1);

        for (int ck = 0; ck < nCk; ++ck) {
            const int rem = nCk - 1 - ck;
            if (rem >= 1) cp_wait1();
            else          cp_wait0();
            __syncthreads();
            if (rem >= 2) issue(ck + 2);

            const uint32_t as0 = smem_u32(As + (ck % NSTG) * HTSZ);
            const uint32_t bs0 = smem_u32(Bs + (ck % NSTG) * HTSZ);
#pragma unroll
            for (int k0 = 0; k0 < GBK; k0 += 16) {
                uint32_t bf[4][2];
#pragma unroll
                for (int np = 0; np < 2; np++) {
                    const uint32_t addr =
                        bs0 + 2 * (b_loff + (wc * 32 + np * 16) * SH + k0);
                    ldsm_x4(bf[2 * np][0], bf[2 * np][1],
                            bf[2 * np + 1][0], bf[2 * np + 1][1], addr);
                }
#pragma unroll
                for (int mt = 0; mt < 4; mt++) {
                    uint32_t a0, a1, a2, a3;
                    const uint32_t addr =
                        as0 + 2 * (a_loff + (wr * 64 + mt * 16) * SH + k0);
                    ldsm_x4(a0, a1, a2, a3, addr);
#pragma unroll
                    for (int nt = 0; nt < 4; nt++)
                        mma_f16(acc[mt][nt][0], acc[mt][nt][1],
                                acc[mt][nt][2], acc[mt][nt][3],
                                a0, a1, a2, a3, bf[nt][0], bf[nt][1]);
                }
            }
        }

        // epilogue
#pragma unroll
        for (int mt = 0; mt < 4; mt++) {
            const int row0 = bm + wr * 64 + mt * 16 + gid;
#pragma unroll
            for (int nt = 0; nt < 4; nt++) {
                const int col = bn + wc * 32 + nt * 8 + tig * 2;
                const float b0 = bias[col], b1 = bias[col + 1];
                if (mode == 0) {
                    __half2 v0 = __floats2half2_rn(acc[mt][nt][0] + b0, acc[mt][nt][1] + b1);
                    __half2 v1 = __floats2half2_rn(acc[mt][nt][2] + b0, acc[mt][nt][3] + b1);
                    *(__half2*)&g_qkv16[(size_t)row0 * N + col] = v0;
                    *(__half2*)&g_qkv16[(size_t)(row0 + 8) * N + col] = v1;
                } else {
                    float2 v0 = make_float2(acc[mt][nt][0] + b0, acc[mt][nt][1] + b1);
                    float2 v1 = make_float2(acc[mt][nt][2] + b0, acc[mt][nt][3] + b1);
                    *(float2*)&C_[(size_t)row0 * N + col] = v0;
                    *(float2*)&C_[(size_t)(row0 + 8) * N + col] = v1;
                }
            }
        }
        __syncthreads();   // protect smem stages before next tile's issue()
    }
}

// ================= fp16 tensor-core flash attention (R10, unchanged) =======
#define KSTR 72
#define KTILE (64 * KSTR)
#define FLASH_SMEM (4 * KTILE * 2 + 512)   // 37376 B

__global__ void __launch_bounds__(128)
flash_h(const int* __restrict__ amask)
{
    extern __shared__ __half hsm[];
    const int qb = 31 - (int)blockIdx.x;
    const int h  = blockIdx.y;
    const int b  = blockIdx.z;
    const int t  = threadIdx.x;
    const int wid = t >> 5, lane = t & 31;
    const int g = lane >> 2, tg = lane & 3;

    __half* const kbuf[2] = { hsm,             hsm + 2 * KTILE };
    __half* const vbuf[2] = { hsm + KTILE,     hsm + 3 * KTILE };
    float*  const msb     = (float*)(hsm + 4 * KTILE);

    const int qrlo = qb * 64 + wid * 16 + g;
    const __half* qlo = g_qkv16 + ((size_t)(b * S_LEN) + qrlo) * 3072 + h * 64;
    const __half* qhi = qlo + (size_t)8 * 3072;
    const __half2 sc2 = __floats2half2_rn(0.125f, 0.125f);
    uint32_t qf[4][4];
#pragma unroll
    for (int kk = 0; kk < 4; kk++) {
        __half2 v0 = __hmul2(*(const __half2*)&qlo[16 * kk + 2 * tg], sc2);
        __half2 v1 = __hmul2(*(const __half2*)&qhi[16 * kk + 2 * tg], sc2);
        __half2 v2 = __hmul2(*(const __half2*)&qlo[16 * kk + 2 * tg + 8], sc2);
        __half2 v3 = __hmul2(*(const __half2*)&qhi[16 * kk + 2 * tg + 8], sc2);
        qf[kk][0] = *(uint32_t*)&v0; qf[kk][1] = *(uint32_t*)&v1;
        qf[kk][2] = *(uint32_t*)&v2; qf[kk][3] = *(uint32_t*)&v3;
    }

    const int kf_loff = ((lane & 7) + ((lane >> 4) & 1) * 8) * KSTR
                        + ((lane >> 3) & 1) * 8;
    const int vf_loff = (lane & 15) * KSTR + ((lane >> 4) & 1) * 8;

    float oa[8][4];
#pragma unroll
    for (int j = 0; j < 8; j++)
#pragma unroll
        for (int i = 0; i < 4; i++) oa[j][i] = 0.f;
    float m0 = -1e30f, m1 = -1e30f, l0 = 0.f, l1 = 0.f;

    auto issue = [&](int jt) {
        const int buf = jt & 1;
        __half* ks = kbuf[buf];
        __half* vs = vbuf[buf];
        const int j0 = jt * 64;
#pragma unroll
        for (int u = 0; u < 4; u++) {
            const int idx = t + 128 * u;
            const int r = idx >> 3, c8 = (idx & 7) * 8;
            const __half* src = g_qkv16 + ((size_t)(b * S_LEN) + j0 + r) * 3072
                                + 1024 + h * 64 + c8;
            cp_async16(smem_u32(ks + r * KSTR + c8), src);
            cp_async16(smem_u32(vs + r * KSTR + c8), src + 1024);
        }
        if (t < 64)
            msb[buf * 64 + t] = amask[b * S_LEN + j0 + t] ? 0.f : NEG;
        cp_commit();
    };

    issue(0);

    for (int jt = 0; jt <= qb; jt++) {
        if (jt < qb) { issue(jt + 1); cp_wait1(); }
        else         { cp_wait0(); }
        __syncthreads();

        const int buf = jt & 1;
        const uint32_t ks0 = smem_u32(kbuf[buf]);
        const uint32_t vs0 = smem_u32(vbuf[buf]);
        const float*   mb  = msb + buf * 64;

        float sc[8][4];
#pragma unroll
        for (int j = 0; j < 8; j++)
#pragma unroll
            for (int i = 0; i < 4; i++) sc[j][i] = 0.f;
#pragma unroll
        for (int kk = 0; kk < 4; kk++) {
            uint32_t kf[8][2];
#pragma unroll
            for (int nb = 0; nb < 4; nb++) {
                const uint32_t addr =
                    ks0 + 2 * (kf_loff + nb * 16 * KSTR + kk * 16);
                ldsm_x4(kf[2 * nb][0], kf[2 * nb][1],
                        kf[2 * nb + 1][0], kf[2 * nb + 1][1], addr);
            }
#pragma unroll
            for (int j = 0; j < 8; j++)
                mma_f16(sc[j][0], sc[j][1], sc[j][2], sc[j][3],
                        qf[kk][0], qf[kk][1], qf[kk][2], qf[kk][3],
                        kf[j][0], kf[j][1]);
        }

        const bool diag = (jt == qb);
        const int rlo = wid * 16 + g, rhi = rlo + 8;
        float tm0 = -1e30f, tm1 = -1e30f;
#pragma unroll
        for (int j = 0; j < 8; j++) {
            const float2 mm = *(const float2*)&mb[8 * j + 2 * tg];
            float c0 = sc[j][0] + mm.x, c1 = sc[j][1] + mm.y;
            float c2 = sc[j][2] + mm.x, c3 = sc[j][3] + mm.y;
            if (diag) {
                const int kv = 8 * j + 2 * tg;
                c0 = (kv     > rlo) ? NEG : c0;
                c1 = (kv + 1 > rlo) ? NEG : c1;
                c2 = (kv     > rhi) ? NEG : c2;
                c3 = (kv + 1 > rhi) ? NEG : c3;
            }
            sc[j][0] = c0; sc[j][1] = c1; sc[j][2] = c2; sc[j][3] = c3;
            tm0 = fmaxf(tm0, fmaxf(c0, c1));
            tm1 = fmaxf(tm1, fmaxf(c2, c3));
        }
        tm0 = fmaxf(tm0, __shfl_xor_sync(0xffffffffu, tm0, 1));
        tm0 = fmaxf(tm0, __shfl_xor_sync(0xffffffffu, tm0, 2));
        tm1 = fmaxf(tm1, __shfl_xor_sync(0xffffffffu, tm1, 1));
        tm1 = fmaxf(tm1, __shfl_xor_sync(0xffffffffu, tm1, 2));

        const float mn0 = fmaxf(m0, tm0), mn1 = fmaxf(m1, tm1);
        const float al0 = __expf(m0 - mn0), al1 = __expf(m1 - mn1);
        float s0 = 0.f, s1 = 0.f;
#pragma unroll
        for (int j = 0; j < 8; j++) {
            sc[j][0] = __expf(sc[j][0] - mn0);
            sc[j][1] = __expf(sc[j][1] - mn0);
            sc[j][2] = __expf(sc[j][2] - mn1);
            sc[j][3] = __expf(sc[j][3] - mn1);
            s0 += sc[j][0] + sc[j][1];
            s1 += sc[j][2] + sc[j][3];
        }
        s0 += __shfl_xor_sync(0xffffffffu, s0, 1);
        s0 += __shfl_xor_sync(0xffffffffu, s0, 2);
        s1 += __shfl_xor_sync(0xffffffffu, s1, 1);
        s1 += __shfl_xor_sync(0xffffffffu, s1, 2);
        l0 = l0 * al0 + s0; l1 = l1 * al1 + s1;
        m0 = mn0; m1 = mn1;
#pragma unroll
        for (int j = 0; j < 8; j++) {
            oa[j][0] *= al0; oa[j][1] *= al0;
            oa[j][2] *= al1; oa[j][3] *= al1;
        }

#pragma unroll
        for (int kk = 0; kk < 4; kk++) {
            const uint32_t a0 = packh2(sc[2 * kk][0],     sc[2 * kk][1]);
            const uint32_t a1 = packh2(sc[2 * kk][2],     sc[2 * kk][3]);
            const uint32_t a2 = packh2(sc[2 * kk + 1][0], sc[2 * kk + 1][1]);
            const uint32_t a3 = packh2(sc[2 * kk + 1][2], sc[2 * kk + 1][3]);
#pragma unroll
            for (int db = 0; db < 4; db++) {
                uint32_t b00, b01, b10, b11;
                const uint32_t addr =
                    vs0 + 2 * (vf_loff + kk * 16 * KSTR + db * 16);
                ldsm_x4_t(b00, b01, b10, b11, addr);
                mma_f16(oa[2 * db][0], oa[2 * db][1], oa[2 * db][2], oa[2 * db][3],
                        a0, a1, a2, a3, b00, b01);
                mma_f16(oa[2 * db + 1][0], oa[2 * db + 1][1],
                        oa[2 * db + 1][2], oa[2 * db + 1][3],
                        a0, a1, a2, a3, b10, b11);
            }
        }
        __syncthreads();
    }

    const float i0 = 1.f / l0, i1 = 1.f / l1;
    __half2* olo = (__half2*)(g_ctx16 + ((size_t)(b * S_LEN) + qrlo) * EMB + h * 64);
    __half2* ohi = (__half2*)((__half*)olo + (size_t)8 * EMB);
#pragma unroll
    for (int j2 = 0; j2 < 8; j2++) {
        const int d2 = 4 * j2 + tg;
        olo[d2] = __floats2half2_rn(oa[j2][0] * i0, oa[j2][1] * i0);
        ohi[d2] = __floats2half2_rn(oa[j2][2] * i1, oa[j2][3] * i1);
    }
}

// =============================== Launch ====================================
extern "C" void kernel_launch(void* const* d_in, const int* in_sizes, int n_in,
                              void* d_out, int out_size)
{
    const float* X     = (const float*)d_in[0];
    const int*   amask = (const int*)  d_in[1];
    const float* Wa    = (const float*)d_in[2];
    const float* ba    = (const float*)d_in[3];
    const float* Wp    = (const float*)d_in[4];
    const float* bp    = (const float*)d_in[5];
    float* out = (float*)d_out;

    cudaFuncSetAttribute(gemm_h, cudaFuncAttributeMaxDynamicSharedMemorySize,
                         GEMM_SMEM);
    cudaFuncSetAttribute(flash_h, cudaFuncAttributeMaxDynamicSharedMemorySize,
                         FLASH_SMEM);

    const int NPERS = 296;   // 2 CTAs/SM x 148 SMs

    // 0) convert inputs to fp16 (one merged launch)
    {
        const int nx = MTOT * EMB / 4, na = 3 * EMB * EMB / 4, np = EMB * EMB / 4;
        const int ntot = nx + na + np;
        cvt_all<<<(ntot + 255) / 256, 256>>>((const float4*)X, (const float4*)Wa,
                                             (const float4*)Wp, nx, na, np);
    }
    // 1) qkv = X @ Wa^T + ba -> g_qkv16 (fp16), persistent
    {
        const int nTiles = (MTOT / GBM) * (3 * EMB / GBN);   // 768
        gemm_h<<<(nTiles < NPERS ? nTiles : NPERS), 256, GEMM_SMEM>>>(
            0, ba, nullptr, MTOT, 3 * EMB, EMB);
    }
    // 2) attention -> g_ctx16 (fp16)
    {
        dim3 grid(S_LEN / 64, NH, BATCH);
        flash_h<<<grid, 128, FLASH_SMEM>>>(amask);
    }
    // 3) out = ctx @ Wp^T + bp (fp32), persistent
    {
        const int nTiles = (MTOT / GBM) * (EMB / GBN);       // 256
        gemm_h<<<(nTiles < NPERS ? nTiles : NPERS), 256, GEMM_SMEM>>>(
            1, bp, out, MTOT, EMB, EMB);
    }
}